// round 12
// baseline (speedup 1.0000x reference)
#include <cuda_runtime.h>
#include <math.h>
#include <stdint.h>

// ---------------------------------------------------------------------------
// Problem constants
// ---------------------------------------------------------------------------
#define BB 16
#define MM 2048
#define FD 128
#define TS 64                        // tile size (rows)
#define NT (MM / TS)                 // 32 tiles
#define NPAIR (NT * (NT + 1) / 2)    // 528 tile pairs (ti <= tj)
#define SSTRIDE 132                  // floats per smem row (128 + 4 pad)
#define SMEM_BYTES (2 * TS * SSTRIDE * 4)        // 67584 B -> 3 CTAs/SM
// zero-fill slice per CTA: 528 CTAs per batch plane
#define ZCHUNK 7944                  // 528 * 7944 = 4194432 >= 2048*2048 (mult of 4)

// Scratch (device globals; no allocation allowed)
__device__ __align__(128) float  g_xnorm[BB * MM * FD];              // 16 MB
// Candidates: [b*M + row][slot(32)] float4 {v1, i1, v2, i2}
__device__ __align__(128) float4 g_cand[(size_t)BB * MM * 32];       // 16.8 MB

// ---------------------------------------------------------------------------
__device__ __forceinline__ unsigned long long fma2(unsigned long long a,
                                                   unsigned long long b,
                                                   unsigned long long c) {
    unsigned long long d;
    asm("fma.rn.f32x2 %0, %1, %2, %3;" : "=l"(d) : "l"(a), "l"(b), "l"(c));
    return d;
}

__device__ __forceinline__ float fold2(unsigned long long v) {
    float lo = __uint_as_float((unsigned)(v & 0xffffffffull));
    float hi = __uint_as_float((unsigned)(v >> 32));
    return lo + hi;
}

// top-2 update, jax tie-break (equal value -> lower index); candidates distinct
__device__ __forceinline__ void top2_update(float v, int k,
                                            float& v1, int& i1, float& v2, int& i2) {
    bool b1 = (v > v1) || (v == v1 && k < i1);
    bool b2 = (v > v2) || (v == v2 && k < i2);
    if (b1)      { v2 = v1; i2 = i1; v1 = v; i1 = k; }
    else if (b2) { v2 = v;  i2 = k; }
}

// butterfly-merge variant: partners carry identical winners -> dedup by index
__device__ __forceinline__ void top2_merge(float v, int k,
                                           float& v1, int& i1, float& v2, int& i2) {
    if (k == i1 || k == i2) return;
    top2_update(v, k, v1, i1, v2, i2);
}

// ---------------------------------------------------------------------------
// Kernel 1: L2-normalize each row (one warp per row)
// ---------------------------------------------------------------------------
__global__ void normalize_kernel(const float* __restrict__ x) {
    int row  = blockIdx.x * 8 + (threadIdx.x >> 5);
    int lane = threadIdx.x & 31;
    float4 v = reinterpret_cast<const float4*>(x + (size_t)row * FD)[lane];
    float ss = v.x * v.x + v.y * v.y + v.z * v.z + v.w * v.w;
    #pragma unroll
    for (int o = 16; o > 0; o >>= 1) ss += __shfl_xor_sync(0xffffffffu, ss, o);
    float inv = 1.0f / fmaxf(sqrtf(ss), 1e-12f);
    v.x *= inv; v.y *= inv; v.z *= inv; v.w *= inv;
    reinterpret_cast<float4*>(g_xnorm + (size_t)row * FD)[lane] = v;
}

// ---------------------------------------------------------------------------
// Kernel 2: symmetric tile-pair GEMM, 64x64 per CTA, 4x4 micro-tile, f32x2.
// Grid: (NPAIR, BB). Block 256 = 16(tx, k) x 16(ty, q). 3 CTAs/SM.
// Emits per-row top-2 candidates row-wise (slot tj) and col-wise (slot ti).
// Also zero-fills a disjoint slice of the output (replaces the memset node).
// ---------------------------------------------------------------------------
__global__ void __launch_bounds__(256, 3) pair_kernel(float* __restrict__ out) {
    extern __shared__ float smem[];
    float* Qs = smem;                      // TS x SSTRIDE
    float* Ks = smem + TS * SSTRIDE;       // TS x SSTRIDE

    const int tid = threadIdx.x;
    const int tx  = tid & 15;
    const int ty  = tid >> 4;
    const int b   = blockIdx.y;

    // ---- zero-fill my slice of out[b] (coalesced float4 stores) ----
    {
        float* O = out + (size_t)b * MM * MM;
        size_t beg = (size_t)blockIdx.x * ZCHUNK;
        size_t end = beg + ZCHUNK;
        if (end > (size_t)MM * MM) end = (size_t)MM * MM;
        const float4 z = make_float4(0.f, 0.f, 0.f, 0.f);
        #pragma unroll 2
        for (size_t i = beg + (size_t)tid * 4; i < end; i += 256 * 4)
            *reinterpret_cast<float4*>(O + i) = z;
    }

    // decode tile pair (ti <= tj)
    int t = blockIdx.x, ti = 0, n = NT;
    while (t >= n) { t -= n; n--; ti++; }
    const int tj    = ti + t;
    const int ibase = ti * TS;
    const int jbase = tj * TS;

    const float* Xb = g_xnorm + (size_t)b * MM * FD;

    // Load Q and K tiles: 64 rows x 32 float4 each (8 float4 per thread each)
    #pragma unroll
    for (int p = 0; p < 8; p++) {
        int idx = tid + p * 256;
        int r = idx >> 5, c4 = idx & 31;
        float4 v = reinterpret_cast<const float4*>(Xb + (size_t)(ibase + r) * FD)[c4];
        *reinterpret_cast<float4*>(Qs + r * SSTRIDE + c4 * 4) = v;
    }
    #pragma unroll
    for (int p = 0; p < 8; p++) {
        int idx = tid + p * 256;
        int r = idx >> 5, c4 = idx & 31;
        float4 v = reinterpret_cast<const float4*>(Xb + (size_t)(jbase + r) * FD)[c4];
        *reinterpret_cast<float4*>(Ks + r * SSTRIDE + c4 * 4) = v;
    }
    __syncthreads();

    // 4x4 micro-tile, packed-f32x2 accumulation (pairs along f).
    unsigned long long acc2[4][4];
    #pragma unroll
    for (int i = 0; i < 4; i++)
        #pragma unroll
        for (int j = 0; j < 4; j++) acc2[i][j] = 0ull;

    #pragma unroll 4
    for (int f = 0; f < FD; f += 4) {
        ulonglong2 q2[4], k2[4];
        #pragma unroll
        for (int i = 0; i < 4; i++)
            q2[i] = *reinterpret_cast<const ulonglong2*>(Qs + (ty + 16 * i) * SSTRIDE + f);
        #pragma unroll
        for (int j = 0; j < 4; j++)
            k2[j] = *reinterpret_cast<const ulonglong2*>(Ks + (tx + 16 * j) * SSTRIDE + f);
        #pragma unroll
        for (int i = 0; i < 4; i++) {
            #pragma unroll
            for (int j = 0; j < 4; j++) {
                acc2[i][j] = fma2(q2[i].x, k2[j].x, acc2[i][j]);
                acc2[i][j] = fma2(q2[i].y, k2[j].y, acc2[i][j]);
            }
        }
    }

    float acc[4][4];
    #pragma unroll
    for (int i = 0; i < 4; i++)
        #pragma unroll
        for (int j = 0; j < 4; j++) acc[i][j] = fold2(acc2[i][j]);

    // zero the diagonal (diagonal tile pairs only)
    if (ti == tj) {
        #pragma unroll
        for (int i = 0; i < 4; i++)
            #pragma unroll
            for (int j = 0; j < 4; j++)
                if (ty + 16 * i == tx + 16 * j) acc[i][j] = 0.0f;
    }

    float* cv = smem;                                     // [64][32]
    int*   ci = reinterpret_cast<int*>(smem) + 64 * 32;

    // ---- Pass 1: row-wise top-2 (q rows of ti vs 64 cols of tj) ----
    __syncthreads();   // done with tiles; reuse smem
    #pragma unroll
    for (int i = 0; i < 4; i++) {
        float v1 = -INFINITY, v2 = -INFINITY;
        int   i1 = 0x7fffffff, i2 = 0x7fffffff;
        #pragma unroll
        for (int j = 0; j < 4; j++)
            top2_update(acc[i][j], jbase + tx + 16 * j, v1, i1, v2, i2);
        int r = ty + 16 * i;
        cv[r * 32 + tx * 2]     = v1; ci[r * 32 + tx * 2]     = i1;
        cv[r * 32 + tx * 2 + 1] = v2; ci[r * 32 + tx * 2 + 1] = i2;
    }
    __syncthreads();
    if (tid < TS) {
        float V1 = -INFINITY, V2 = -INFINITY;
        int   I1 = 0x7fffffff, I2 = 0x7fffffff;
        #pragma unroll 8
        for (int c = 0; c < 32; c++)
            top2_update(cv[tid * 32 + c], ci[tid * 32 + c], V1, I1, V2, I2);
        g_cand[(size_t)(b * MM + ibase + tid) * 32 + tj] =
            make_float4(V1, __int_as_float(I1), V2, __int_as_float(I2));
    }

    // ---- Pass 2: col-wise top-2 (k rows of tj vs 64 q cols of ti) ----
    if (ti != tj) {
        __syncthreads();
        #pragma unroll
        for (int j = 0; j < 4; j++) {
            float v1 = -INFINITY, v2 = -INFINITY;
            int   i1 = 0x7fffffff, i2 = 0x7fffffff;
            #pragma unroll
            for (int i = 0; i < 4; i++)
                top2_update(acc[i][j], ibase + ty + 16 * i, v1, i1, v2, i2);
            int c = tx + 16 * j;
            cv[c * 32 + ty * 2]     = v1; ci[c * 32 + ty * 2]     = i1;
            cv[c * 32 + ty * 2 + 1] = v2; ci[c * 32 + ty * 2 + 1] = i2;
        }
        __syncthreads();
        if (tid < TS) {
            float V1 = -INFINITY, V2 = -INFINITY;
            int   I1 = 0x7fffffff, I2 = 0x7fffffff;
            #pragma unroll 8
            for (int c = 0; c < 32; c++)
                top2_update(cv[tid * 32 + c], ci[tid * 32 + c], V1, I1, V2, I2);
            g_cand[(size_t)(b * MM + jbase + tid) * 32 + ti] =
                make_float4(V1, __int_as_float(I1), V2, __int_as_float(I2));
        }
    }
}

// ---------------------------------------------------------------------------
// Kernel 3: per-row reduce of 32 candidate slots (all valid) -> top-2 ->
// symmetric scatter. One warp per row; lane L owns slot L.
// ---------------------------------------------------------------------------
__global__ void reduce_kernel(float* __restrict__ out) {
    int row  = blockIdx.x * 8 + (threadIdx.x >> 5);
    int lane = threadIdx.x & 31;
    int m = row & (MM - 1);

    float4 c = g_cand[(size_t)row * 32 + lane];
    float v1 = c.x;              int i1 = __float_as_int(c.y);
    float v2 = -INFINITY;        int i2 = 0x7fffffff;
    top2_update(c.z, __float_as_int(c.w), v1, i1, v2, i2);

    #pragma unroll
    for (int o = 16; o > 0; o >>= 1) {
        float ov1 = __shfl_xor_sync(0xffffffffu, v1, o);
        float ov2 = __shfl_xor_sync(0xffffffffu, v2, o);
        int   oi1 = __shfl_xor_sync(0xffffffffu, i1, o);
        int   oi2 = __shfl_xor_sync(0xffffffffu, i2, o);
        top2_merge(ov1, oi1, v1, i1, v2, i2);
        top2_merge(ov2, oi2, v1, i1, v2, i2);
    }
    if (lane == 0) {
        int b = row >> 11;
        float* O = out + (size_t)b * MM * MM;
        atomicAdd(O + (size_t)m * MM + i1, 0.5f * v1);
        atomicAdd(O + (size_t)i1 * MM + m, 0.5f * v1);
        atomicAdd(O + (size_t)m * MM + i2, 0.5f * v2);
        atomicAdd(O + (size_t)i2 * MM + m, 0.5f * v2);
    }
}

// ---------------------------------------------------------------------------
extern "C" void kernel_launch(void* const* d_in, const int* in_sizes, int n_in,
                              void* d_out, int out_size) {
    const float* x = (const float*)d_in[0];
    float* out = (float*)d_out;

    normalize_kernel<<<(BB * MM) / 8, 256>>>(x);

    cudaFuncSetAttribute(pair_kernel,
                         cudaFuncAttributeMaxDynamicSharedMemorySize, SMEM_BYTES);
    dim3 grid(NPAIR, BB);
    pair_kernel<<<grid, 256, SMEM_BYTES>>>(out);

    reduce_kernel<<<(BB * MM) / 8, 256>>>(out);
}

// round 13
// speedup vs baseline: 1.0325x; 1.0325x over previous
#include <cuda_runtime.h>
#include <math.h>
#include <stdint.h>

// ---------------------------------------------------------------------------
// Problem constants
// ---------------------------------------------------------------------------
#define BB 16
#define MM 2048
#define FD 128
#define TS 128                       // tile size (rows) -- 128x128 output/CTA
#define NT (MM / TS)                 // 16 tiles
#define NPAIR (NT * (NT + 1) / 2)    // 136 tile pairs (ti <= tj)
#define FH 64                        // f processed in two halves of 64
#define SSTRIDE 68                   // floats per smem row (64 + 4 pad)
#define SMEM_BYTES (2 * TS * SSTRIDE * 4)   // 69632 B -> 2 CTAs/SM
// zero-fill slice per CTA: 136 CTAs per batch plane
#define ZCHUNK 30844                 // 136 * 30844 = 4194784 >= 2048*2048 (mult 4)

// Scratch (device globals; no allocation allowed)
__device__ __align__(128) float  g_xnorm[BB * MM * FD];              // 16 MB
// Candidates: [b*M + row][slot(16)] float4 {v1, i1, v2, i2}
__device__ __align__(128) float4 g_cand[(size_t)BB * MM * NT];       // 8.4 MB

// ---------------------------------------------------------------------------
// top-2 update, jax tie-break (equal value -> lower index); candidates distinct
__device__ __forceinline__ void top2_update(float v, int k,
                                            float& v1, int& i1, float& v2, int& i2) {
    bool b1 = (v > v1) || (v == v1 && k < i1);
    bool b2 = (v > v2) || (v == v2 && k < i2);
    if (b1)      { v2 = v1; i2 = i1; v1 = v; i1 = k; }
    else if (b2) { v2 = v;  i2 = k; }
}

// butterfly-merge variant: partners carry identical winners -> dedup by index
__device__ __forceinline__ void top2_merge(float v, int k,
                                           float& v1, int& i1, float& v2, int& i2) {
    if (k == i1 || k == i2) return;
    top2_update(v, k, v1, i1, v2, i2);
}

// ---------------------------------------------------------------------------
// Kernel 1: L2-normalize each row (one warp per row)
// ---------------------------------------------------------------------------
__global__ void normalize_kernel(const float* __restrict__ x) {
    int row  = blockIdx.x * 8 + (threadIdx.x >> 5);
    int lane = threadIdx.x & 31;
    float4 v = reinterpret_cast<const float4*>(x + (size_t)row * FD)[lane];
    float ss = v.x * v.x + v.y * v.y + v.z * v.z + v.w * v.w;
    #pragma unroll
    for (int o = 16; o > 0; o >>= 1) ss += __shfl_xor_sync(0xffffffffu, ss, o);
    float inv = 1.0f / fmaxf(sqrtf(ss), 1e-12f);
    v.x *= inv; v.y *= inv; v.z *= inv; v.w *= inv;
    reinterpret_cast<float4*>(g_xnorm + (size_t)row * FD)[lane] = v;
}

// ---------------------------------------------------------------------------
// Kernel 2: symmetric tile-pair GEMM, 128x128 per CTA, 8x8 micro-tile,
// f streamed through smem in two 64-wide halves. 2 CTAs/SM.
// Grid: (NPAIR, BB). Block 256 = 16(tx) x 16(ty).
// Emits per-row top-2 candidates row-wise (slot tj) and col-wise (slot ti);
// zero-fills a disjoint slice of the output plane.
// ---------------------------------------------------------------------------
__global__ void __launch_bounds__(256, 2) pair_kernel(float* __restrict__ out) {
    extern __shared__ float smem[];
    float* Qs = smem;                      // TS x SSTRIDE
    float* Ks = smem + TS * SSTRIDE;       // TS x SSTRIDE

    const int tid = threadIdx.x;
    const int tx  = tid & 15;
    const int ty  = tid >> 4;
    const int b   = blockIdx.y;

    // ---- zero-fill my slice of out[b] ----
    {
        float* O = out + (size_t)b * MM * MM;
        size_t beg = (size_t)blockIdx.x * ZCHUNK;
        size_t end = beg + ZCHUNK;
        if (end > (size_t)MM * MM) end = (size_t)MM * MM;
        const float4 z = make_float4(0.f, 0.f, 0.f, 0.f);
        #pragma unroll 2
        for (size_t i = beg + (size_t)tid * 4; i < end; i += 256 * 4)
            *reinterpret_cast<float4*>(O + i) = z;
    }

    // decode tile pair (ti <= tj)
    int t = blockIdx.x, ti = 0, n = NT;
    while (t >= n) { t -= n; n--; ti++; }
    const int tj    = ti + t;
    const int ibase = ti * TS;
    const int jbase = tj * TS;

    const float* Xb = g_xnorm + (size_t)b * MM * FD;
    const float* Kt = (ti == tj) ? Qs : Ks;

    float acc[8][8];
    #pragma unroll
    for (int i = 0; i < 8; i++)
        #pragma unroll
        for (int j = 0; j < 8; j++) acc[i][j] = 0.0f;

    // ---- two f-halves streamed through smem ----
    for (int fh = 0; fh < 2; fh++) {
        if (fh) __syncthreads();           // previous half fully consumed
        // load Q half: 128 rows x 16 float4 (8 per thread), coalesced
        #pragma unroll
        for (int p = 0; p < 8; p++) {
            int idx = tid + p * 256;
            int r = idx >> 4, c4 = idx & 15;
            float4 v = reinterpret_cast<const float4*>(
                Xb + (size_t)(ibase + r) * FD + fh * FH)[c4];
            *reinterpret_cast<float4*>(Qs + r * SSTRIDE + c4 * 4) = v;
        }
        if (ti != tj) {
            #pragma unroll
            for (int p = 0; p < 8; p++) {
                int idx = tid + p * 256;
                int r = idx >> 4, c4 = idx & 15;
                float4 v = reinterpret_cast<const float4*>(
                    Xb + (size_t)(jbase + r) * FD + fh * FH)[c4];
                *reinterpret_cast<float4*>(Ks + r * SSTRIDE + c4 * 4) = v;
            }
        }
        __syncthreads();

        #pragma unroll 2
        for (int f = 0; f < FH; f += 4) {
            float4 q4[8];
            #pragma unroll
            for (int i = 0; i < 8; i++)
                q4[i] = *reinterpret_cast<const float4*>(Qs + (ty + 16 * i) * SSTRIDE + f);
            // k in two register-halves to bound pressure
            #pragma unroll
            for (int jh = 0; jh < 2; jh++) {
                float4 k4[4];
                #pragma unroll
                for (int j = 0; j < 4; j++)
                    k4[j] = *reinterpret_cast<const float4*>(
                        Kt + (tx + 16 * (jh * 4 + j)) * SSTRIDE + f);
                #pragma unroll
                for (int i = 0; i < 8; i++) {
                    #pragma unroll
                    for (int j = 0; j < 4; j++) {
                        float* a = &acc[i][jh * 4 + j];
                        *a += q4[i].x * k4[j].x;
                        *a += q4[i].y * k4[j].y;
                        *a += q4[i].z * k4[j].z;
                        *a += q4[i].w * k4[j].w;
                    }
                }
            }
        }
    }

    // zero the diagonal (diagonal tile pairs only)
    if (ti == tj) {
        #pragma unroll
        for (int i = 0; i < 8; i++)
            #pragma unroll
            for (int j = 0; j < 8; j++)
                if (ty + 16 * i == tx + 16 * j) acc[i][j] = 0.0f;
    }

    float* cv = smem;                                     // [128][32]
    int*   ci = reinterpret_cast<int*>(smem) + 128 * 32;  // [128][32]

    // ---- Pass 1: row-wise top-2 (q rows of ti vs 128 cols of tj) ----
    __syncthreads();   // done with tiles; reuse smem
    #pragma unroll
    for (int i = 0; i < 8; i++) {
        float v1 = -INFINITY, v2 = -INFINITY;
        int   i1 = 0x7fffffff, i2 = 0x7fffffff;
        #pragma unroll
        for (int j = 0; j < 8; j++)
            top2_update(acc[i][j], jbase + tx + 16 * j, v1, i1, v2, i2);
        int r = ty + 16 * i;
        cv[r * 32 + tx * 2]     = v1; ci[r * 32 + tx * 2]     = i1;
        cv[r * 32 + tx * 2 + 1] = v2; ci[r * 32 + tx * 2 + 1] = i2;
    }
    __syncthreads();
    if (tid < TS) {
        float V1 = -INFINITY, V2 = -INFINITY;
        int   I1 = 0x7fffffff, I2 = 0x7fffffff;
        #pragma unroll 8
        for (int c = 0; c < 32; c++)
            top2_update(cv[tid * 32 + c], ci[tid * 32 + c], V1, I1, V2, I2);
        g_cand[(size_t)(b * MM + ibase + tid) * NT + tj] =
            make_float4(V1, __int_as_float(I1), V2, __int_as_float(I2));
    }

    // ---- Pass 2: col-wise top-2 (k rows of tj vs 128 q cols of ti) ----
    if (ti != tj) {
        __syncthreads();
        #pragma unroll
        for (int j = 0; j < 8; j++) {
            float v1 = -INFINITY, v2 = -INFINITY;
            int   i1 = 0x7fffffff, i2 = 0x7fffffff;
            #pragma unroll
            for (int i = 0; i < 8; i++)
                top2_update(acc[i][j], ibase + ty + 16 * i, v1, i1, v2, i2);
            int c = tx + 16 * j;
            cv[c * 32 + ty * 2]     = v1; ci[c * 32 + ty * 2]     = i1;
            cv[c * 32 + ty * 2 + 1] = v2; ci[c * 32 + ty * 2 + 1] = i2;
        }
        __syncthreads();
        if (tid < TS) {
            float V1 = -INFINITY, V2 = -INFINITY;
            int   I1 = 0x7fffffff, I2 = 0x7fffffff;
            #pragma unroll 8
            for (int c = 0; c < 32; c++)
                top2_update(cv[tid * 32 + c], ci[tid * 32 + c], V1, I1, V2, I2);
            g_cand[(size_t)(b * MM + jbase + tid) * NT + ti] =
                make_float4(V1, __int_as_float(I1), V2, __int_as_float(I2));
        }
    }
}

// ---------------------------------------------------------------------------
// Kernel 3: per-row reduce of 16 candidate slots -> top-2 -> symmetric
// scatter. One warp per row; lanes 0-15 own one slot each.
// ---------------------------------------------------------------------------
__global__ void reduce_kernel(float* __restrict__ out) {
    int row  = blockIdx.x * 8 + (threadIdx.x >> 5);
    int lane = threadIdx.x & 31;
    int m = row & (MM - 1);

    float v1 = -INFINITY, v2 = -INFINITY;
    int   i1 = 0x7fffffff, i2 = 0x7fffffff;
    if (lane < NT) {
        float4 c = g_cand[(size_t)row * NT + lane];
        v1 = c.x; i1 = __float_as_int(c.y);
        top2_update(c.z, __float_as_int(c.w), v1, i1, v2, i2);
    }
    #pragma unroll
    for (int o = 16; o > 0; o >>= 1) {
        float ov1 = __shfl_xor_sync(0xffffffffu, v1, o);
        float ov2 = __shfl_xor_sync(0xffffffffu, v2, o);
        int   oi1 = __shfl_xor_sync(0xffffffffu, i1, o);
        int   oi2 = __shfl_xor_sync(0xffffffffu, i2, o);
        top2_merge(ov1, oi1, v1, i1, v2, i2);
        top2_merge(ov2, oi2, v1, i1, v2, i2);
    }
    if (lane == 0) {
        int b = row >> 11;
        float* O = out + (size_t)b * MM * MM;
        atomicAdd(O + (size_t)m * MM + i1, 0.5f * v1);
        atomicAdd(O + (size_t)i1 * MM + m, 0.5f * v1);
        atomicAdd(O + (size_t)m * MM + i2, 0.5f * v2);
        atomicAdd(O + (size_t)i2 * MM + m, 0.5f * v2);
    }
}

// ---------------------------------------------------------------------------
extern "C" void kernel_launch(void* const* d_in, const int* in_sizes, int n_in,
                              void* d_out, int out_size) {
    const float* x = (const float*)d_in[0];
    float* out = (float*)d_out;

    normalize_kernel<<<(BB * MM) / 8, 256>>>(x);

    cudaFuncSetAttribute(pair_kernel,
                         cudaFuncAttributeMaxDynamicSharedMemorySize, SMEM_BYTES);
    dim3 grid(NPAIR, BB);
    pair_kernel<<<grid, 256, SMEM_BYTES>>>(out);

    reduce_kernel<<<(BB * MM) / 8, 256>>>(out);
}